// round 8
// baseline (speedup 1.0000x reference)
#include <cuda_runtime.h>

#define kB 16
#define kL 1444
#define kD 128
#define kD2 64          // float2 lanes per position
#define kC 21
#define kChunks 152     // 76 chunks of len 10, then 76 of len 9
#define kSeg 8          // 152 = 8 segments * 19 chunks
#define kSegLen 19
#define kT 64
#define kQP 22          // padded Q row stride

typedef unsigned long long ull;

// Device scratch (no allocations allowed)
__device__ float g_cs [kB*kChunks*kC*kD];  // chunk class sums -> local (per-seg) exclusive prefix
__device__ float g_seg[kB*kC*kSeg*kD];     // segment totals -> segment exclusive bases
__device__ float g_tot[kB*kC*kD];          // per-batch class totals
__device__ float g_R  [kB*kC*kD];          // R[b][a][d] = sum_c P[c][a]*tot[b][c][d]
__device__ int   g_cls[kB*kL];
__device__ unsigned g_cnt[kB];             // per-batch arrival counters (self-resetting)

static __device__ __forceinline__ int chunkStart(int k){
    return k < 76 ? 10*k : 760 + 9*(k - 76);
}

// ---- packed f32x2 helpers ---------------------------------------------------
static __device__ __forceinline__ ull fadd2(ull a, ull b){
    ull r; asm("add.rn.f32x2 %0,%1,%2;" : "=l"(r) : "l"(a), "l"(b)); return r;
}
static __device__ __forceinline__ ull ffma2x(ull a, ull b, ull c){
    ull r; asm("fma.rn.f32x2 %0,%1,%2,%3;" : "=l"(r) : "l"(a), "l"(b), "l"(c)); return r;
}
static __device__ __forceinline__ ull dup2(float x){
    ull r; asm("mov.b64 %0,{%1,%1};" : "=l"(r) : "f"(x)); return r;
}
static __device__ __forceinline__ ull ldcg64(const float* p){
    ull r; asm volatile("ld.global.cg.b64 %0,[%1];" : "=l"(r) : "l"(p)); return r;
}
static __device__ __forceinline__ void stcg64(float* p, ull v){
    asm volatile("st.global.cg.b64 [%0],%1;" :: "l"(p), "l"(v));
}

// ===========================================================================
// K0: dtype detection + index conversion (once).
__global__ void __launch_bounds__(128) convert_kernel(const void* __restrict__ cls)
{
    int bad = 0;
    const ull* p64 = (const ull*)cls;
    for (int i = threadIdx.x; i < 256; i += 128)
        if (p64[i] > 20ULL) bad = 1;           // impossible under int64 layout
    int is32 = __syncthreads_or(bad);

    int i = blockIdx.x * 128 + threadIdx.x;
    if (i < kB*kL)
        g_cls[i] = is32 ? ((const int*)cls)[i]
                        : (int)((const long long*)cls)[i];
}

// ===========================================================================
// K1: per-chunk class sums + source passthrough.
template<int CL>
static __device__ __forceinline__ void sum_body(
    const float* __restrict__ src, float* __restrict__ outS,
    int t, int b, int chunk, int* clsS, ull* acc)
{
    const int posBase = b*kL + chunkStart(chunk);
    if (t < CL) clsS[t] = g_cls[posBase + t];
    #pragma unroll
    for (int c = 0; c < kC; c++) acc[c*kT + t] = 0ULL;
    __syncthreads();

    const ull* sp = (const ull*)src + (size_t)posBase*kD2 + t;
    ull s[CL];
    #pragma unroll
    for (int i = 0; i < CL; i++) s[i] = sp[(size_t)i*kD2];

    if (outS){
        ull* osp = (ull*)outS + (size_t)posBase*kD2 + t;
        #pragma unroll
        for (int i = 0; i < CL; i++) osp[(size_t)i*kD2] = s[i];
    }

    #pragma unroll
    for (int i = 0; i < CL; i++){
        int c = clsS[i];                              // warp-uniform
        acc[c*kT + t] = fadd2(acc[c*kT + t], s[i]);   // private slot
    }

    float* cs = g_cs + ((size_t)(b*kChunks + chunk)*kC)*kD + 2*t;
    #pragma unroll
    for (int c = 0; c < kC; c++) stcg64(cs + (size_t)c*kD, acc[c*kT + t]);
}

__global__ void __launch_bounds__(kT) sum_kernel(const float* __restrict__ src,
                                                 float* __restrict__ outS)
{
    __shared__ int clsS[10];
    __shared__ ull acc[kC*kT];
    const int t = threadIdx.x, chunk = blockIdx.x, b = blockIdx.y;
    if (chunk < 76) sum_body<10>(src, outS, t, b, chunk, clsS, acc);
    else            sum_body<9> (src, outS, t, b, chunk, clsS, acc);
}

// ===========================================================================
// K2a: local exclusive scan of 19 chunks per (b,c,seg); emits segment total.
__global__ void __launch_bounds__(kT) scanlocal_kernel()
{
    const int t = threadIdx.x;
    const int bc = blockIdx.x;                 // 0..335
    const int seg = blockIdx.y;                // 0..7
    const int b = bc / kC, c = bc % kC;

    float* base = g_cs + ((size_t)(b*kChunks + seg*kSegLen)*kC + c)*kD + 2*t;
    const size_t stride = (size_t)kC*kD;

    ull v[kSegLen];
    #pragma unroll
    for (int k = 0; k < kSegLen; k++) v[k] = ldcg64(base + (size_t)k*stride);
    ull run = 0ULL;
    #pragma unroll
    for (int k = 0; k < kSegLen; k++){
        stcg64(base + (size_t)k*stride, run);
        run = fadd2(run, v[k]);
    }
    stcg64(g_seg + (((size_t)(b*kC + c))*kSeg + seg)*kD + 2*t, run);
}

// ===========================================================================
// K2b: scan segment totals per (b,c); last CTA per batch computes R.
__global__ void __launch_bounds__(kT) scanseg_kernel(const float* __restrict__ P)
{
    const int t = threadIdx.x;
    const int bc = blockIdx.x;
    const int b = bc / kC, c = bc % kC;

    float* sg = g_seg + ((size_t)(b*kC + c))*kSeg*kD + 2*t;
    ull v[kSeg];
    #pragma unroll
    for (int k = 0; k < kSeg; k++) v[k] = ldcg64(sg + (size_t)k*kD);
    ull run = 0ULL;
    #pragma unroll
    for (int k = 0; k < kSeg; k++){
        stcg64(sg + (size_t)k*kD, run);       // segment exclusive base
        run = fadd2(run, v[k]);
    }
    stcg64(g_tot + ((size_t)b*kC + c)*kD + 2*t, run);

    __threadfence();
    __shared__ int isLast;
    if (t == 0){
        unsigned old = atomicAdd(&g_cnt[b], 1u);
        isLast = (old == (unsigned)(kC - 1));
    }
    __syncthreads();

    if (isLast){
        __threadfence();
        __shared__ float Psh[kC*kC];
        for (int i = t; i < kC*kC; i += kT) Psh[i] = P[i];

        ull tot2[kC];
        #pragma unroll
        for (int cc = 0; cc < kC; cc++)
            tot2[cc] = ldcg64(g_tot + ((size_t)b*kC + cc)*kD + 2*t);
        __syncthreads();

        #pragma unroll
        for (int a = 0; a < kC; a++){
            ull r = 0ULL;
            #pragma unroll
            for (int cc = 0; cc < kC; cc++)
                r = ffma2x(dup2(Psh[cc*kC + a]), tot2[cc], r);
            stcg64(g_R + ((size_t)b*kC + a)*kD + 2*t, r);
        }
        if (t == 0) g_cnt[b] = 0u;            // self-reset for graph replay
    }
}

// ===========================================================================
// K3: fused[i] = QB[c_i] + coef[c_i]*s_i + sum_{j<i} M[i][j]*s_j
template<int CL>
static __device__ __forceinline__ void main_body(
    const float* __restrict__ src, float* __restrict__ outF,
    int t, int b, int chunk,
    ull* Q2, ull* coef2, ull* M2, ull* QBs, int* clsS, int* presentS)
{
    const int posBase = b*kL + chunkStart(chunk);
    if (t < CL) clsS[t] = g_cls[posBase + t];
    __syncthreads();

    // triangle coeffs M2[tri(i)+j] = Q[c_i, c_j], j<i  (<=45 entries)
    constexpr int TRI = CL*(CL-1)/2;
    if (t < TRI){
        int i = 1;
        while (i*(i+1)/2 <= t) i++;
        int j = t - i*(i-1)/2;
        M2[t] = Q2[clsS[i]*kQP + clsS[j]];
    }

    if (t == 0){
        unsigned mask = 0;
        #pragma unroll
        for (int i = 0; i < CL; i++) mask |= 1u << clsS[i];
        int n = 0;
        while (mask){ int a = __ffs(mask) - 1; mask &= mask - 1; presentS[1 + n++] = a; }
        presentS[0] = n;
    }

    // R preload (MLP over 21)
    const float* Rr = g_R + ((size_t)b*kC)*kD + 2*t;
    #pragma unroll
    for (int a = 0; a < kC; a++) QBs[a*kT + t] = ldcg64(Rr + (size_t)a*kD);

    // base = seg exclusive base + local exclusive prefix
    ull base[kC];
    {
        const int seg = chunk / kSegLen;
        const float* cs = g_cs  + ((size_t)(b*kChunks + chunk)*kC)*kD + 2*t;
        const float* sb = g_seg + (((size_t)(b*kC))*kSeg + seg)*kD + 2*t;
        #pragma unroll
        for (int c = 0; c < kC; c++)
            base[c] = fadd2(ldcg64(cs + (size_t)c*kD),
                            ldcg64(sb + (size_t)c*kSeg*kD));
    }
    __syncthreads();

    // QB[a] for present classes only (warp-uniform count)
    const int nd = presentS[0];
    for (int k = 0; k < nd; k++){
        int a = presentS[1 + k];
        ull r = QBs[a*kT + t];
        #pragma unroll
        for (int c = 0; c < kC; c++)
            r = ffma2x(Q2[a*kQP + c], base[c], r);
        QBs[a*kT + t] = r;
    }

    const ull* sp = (const ull*)src + (size_t)posBase*kD2 + t;
    ull* fp = (ull*)outF + (size_t)posBase*kD2 + t;
    ull s[CL];
    #pragma unroll
    for (int i = 0; i < CL; i++) s[i] = sp[(size_t)i*kD2];

    #pragma unroll
    for (int i = 0; i < CL; i++){
        int c = clsS[i];                       // warp-uniform
        ull r = QBs[c*kT + t];
        r = ffma2x(coef2[c], s[i], r);
        const int tb = i*(i-1)/2;
        #pragma unroll
        for (int j = 0; j < i; j++)
            r = ffma2x(M2[tb + j], s[j], r);
        fp[(size_t)i*kD2] = r;
    }
}

__global__ void __launch_bounds__(kT) main_kernel(const float* __restrict__ P,
                                                  const float* __restrict__ src,
                                                  float* __restrict__ outF)
{
    __shared__ ull Q2[kC*kQP];
    __shared__ ull coef2[kC];
    __shared__ ull M2[45];
    __shared__ ull QBs[kC*kT];
    __shared__ int clsS[10];
    __shared__ int presentS[kC + 1];

    const int t = threadIdx.x, chunk = blockIdx.x, b = blockIdx.y;

    for (int idx = t; idx < kC*kC; idx += kT){
        int a = idx / kC, c = idx % kC;
        Q2[a*kQP + c] = dup2(P[a*kC + c] - P[c*kC + a]);
    }
    if (t < kC) coef2[t] = dup2((t != 0 ? 1.0f : 0.0f) - P[t*kC + t]);
    __syncthreads();

    if (chunk < 76) main_body<10>(src, outF, t, b, chunk, Q2, coef2, M2, QBs, clsS, presentS);
    else            main_body<9> (src, outF, t, b, chunk, Q2, coef2, M2, QBs, clsS, presentS);
}

// ===========================================================================
extern "C" void kernel_launch(void* const* d_in, const int* in_sizes, int n_in,
                              void* d_out, int out_size)
{
    const float* P   = (const float*)d_in[0];  // cls_r_prob [C,C]
    const float* src = (const float*)d_in[1];  // source [B,L,D]
    const void*  cls = d_in[2];                // class_idx [B,L]

    float* outF = (float*)d_out;
    const long long fusedElems = (long long)kB*kL*kD;
    float* outS = ((long long)out_size >= 2*fusedElems) ? (outF + fusedElems) : nullptr;

    convert_kernel  <<<(kB*kL + 127)/128, 128>>>(cls);
    sum_kernel      <<<dim3(kChunks, kB), kT>>>(src, outS);
    scanlocal_kernel<<<dim3(kB*kC, kSeg), kT>>>();
    scanseg_kernel  <<<kB*kC, kT>>>(P);
    main_kernel     <<<dim3(kChunks, kB), kT>>>(P, src, outF);
}

// round 9
// speedup vs baseline: 1.0985x; 1.0985x over previous
#include <cuda_runtime.h>

#define kB 16
#define kL 1444
#define kD 128
#define kD2 64          // float2 lanes per position
#define kC 21
#define kChunks 152     // 76 chunks of len 10, then 76 of len 9
#define kT 64
#define kQP 22          // padded Q row stride
#define kWaves 8        // 152 = 8 waves * 19 chunks in the scan

typedef unsigned long long ull;

// Device scratch (no allocations allowed)
__device__ float g_cs [kB*kChunks*kC*kD];  // chunk class sums -> exclusive prefix after scan
__device__ float g_tot[kB*kC*kD];          // per-batch class totals
__device__ float g_R  [kB*kC*kD];          // R[b][a][d] = sum_c P[c][a]*tot[b][c][d]
__device__ int   g_cls[kB*kL];
__device__ unsigned g_cnt[kB];             // per-batch arrival counters (self-resetting)

static __device__ __forceinline__ int chunkStart(int k){
    return k < 76 ? 10*k : 760 + 9*(k - 76);
}

// ---- packed f32x2 helpers ---------------------------------------------------
static __device__ __forceinline__ ull fadd2(ull a, ull b){
    ull r; asm("add.rn.f32x2 %0,%1,%2;" : "=l"(r) : "l"(a), "l"(b)); return r;
}
static __device__ __forceinline__ ull ffma2x(ull a, ull b, ull c){
    ull r; asm("fma.rn.f32x2 %0,%1,%2,%3;" : "=l"(r) : "l"(a), "l"(b), "l"(c)); return r;
}
static __device__ __forceinline__ ull dup2(float x){
    ull r; asm("mov.b64 %0,{%1,%1};" : "=l"(r) : "f"(x)); return r;
}
static __device__ __forceinline__ ull ldcg64(const float* p){
    ull r; asm volatile("ld.global.cg.b64 %0,[%1];" : "=l"(r) : "l"(p)); return r;
}
static __device__ __forceinline__ void stcg64(float* p, ull v){
    asm volatile("st.global.cg.b64 [%0],%1;" :: "l"(p), "l"(v));
}

// ===========================================================================
// K0: dtype detection + index conversion (once).
__global__ void __launch_bounds__(128) convert_kernel(const void* __restrict__ cls)
{
    int bad = 0;
    const ull* p64 = (const ull*)cls;
    for (int i = threadIdx.x; i < 256; i += 128)
        if (p64[i] > 20ULL) bad = 1;           // impossible under int64 layout
    int is32 = __syncthreads_or(bad);

    int i = blockIdx.x * 128 + threadIdx.x;
    if (i < kB*kL)
        g_cls[i] = is32 ? ((const int*)cls)[i]
                        : (int)((const long long*)cls)[i];
}

// ===========================================================================
// K1: per-chunk class sums + source passthrough.
template<int CL>
static __device__ __forceinline__ void sum_body(
    const float* __restrict__ src, float* __restrict__ outS,
    int t, int b, int chunk, int* clsS, ull* acc)
{
    const int posBase = b*kL + chunkStart(chunk);
    if (t < CL) clsS[t] = g_cls[posBase + t];
    #pragma unroll
    for (int c = 0; c < kC; c++) acc[c*kT + t] = 0ULL;
    __syncthreads();

    const ull* sp = (const ull*)src + (size_t)posBase*kD2 + t;
    ull s[CL];
    #pragma unroll
    for (int i = 0; i < CL; i++) s[i] = sp[(size_t)i*kD2];

    if (outS){
        ull* osp = (ull*)outS + (size_t)posBase*kD2 + t;
        #pragma unroll
        for (int i = 0; i < CL; i++) osp[(size_t)i*kD2] = s[i];
    }

    #pragma unroll
    for (int i = 0; i < CL; i++){
        int c = clsS[i];                              // warp-uniform
        acc[c*kT + t] = fadd2(acc[c*kT + t], s[i]);   // private slot
    }

    float* cs = g_cs + ((size_t)(b*kChunks + chunk)*kC)*kD + 2*t;
    #pragma unroll
    for (int c = 0; c < kC; c++) stcg64(cs + (size_t)c*kD, acc[c*kT + t]);
}

__global__ void __launch_bounds__(kT) sum_kernel(const float* __restrict__ src,
                                                 float* __restrict__ outS)
{
    __shared__ int clsS[10];
    __shared__ ull acc[kC*kT];
    const int t = threadIdx.x, chunk = blockIdx.x, b = blockIdx.y;
    if (chunk < 76) sum_body<10>(src, outS, t, b, chunk, clsS, acc);
    else            sum_body<9> (src, outS, t, b, chunk, clsS, acc);
}

// ===========================================================================
// K2: single-level exclusive scan over all 152 chunks per (b,c);
//     last-arriving CTA per batch computes R.
__global__ void __launch_bounds__(kT) scan_kernel(const float* __restrict__ P)
{
    const int t = threadIdx.x;
    const int bc = blockIdx.x;                // 0..335
    const int b = bc / kC, c = bc % kC;

    float* base = g_cs + ((size_t)b*kChunks*kC + c)*kD + 2*t;
    const size_t stride = (size_t)kC*kD;

    ull run = 0ULL;
    #pragma unroll
    for (int w = 0; w < kWaves; w++){
        ull v[19];
        #pragma unroll
        for (int k = 0; k < 19; k++) v[k] = ldcg64(base + (size_t)(w*19 + k)*stride);
        #pragma unroll
        for (int k = 0; k < 19; k++){
            stcg64(base + (size_t)(w*19 + k)*stride, run);
            run = fadd2(run, v[k]);
        }
    }
    stcg64(g_tot + ((size_t)b*kC + c)*kD + 2*t, run);

    __threadfence();
    __shared__ int isLast;
    if (t == 0){
        unsigned old = atomicAdd(&g_cnt[b], 1u);
        isLast = (old == (unsigned)(kC - 1));
    }
    __syncthreads();

    if (isLast){
        __threadfence();
        __shared__ float Psh[kC*kC];
        for (int i = t; i < kC*kC; i += kT) Psh[i] = P[i];

        ull tot2[kC];
        #pragma unroll
        for (int cc = 0; cc < kC; cc++)
            tot2[cc] = ldcg64(g_tot + ((size_t)b*kC + cc)*kD + 2*t);
        __syncthreads();

        #pragma unroll
        for (int a = 0; a < kC; a++){
            ull r = 0ULL;
            #pragma unroll
            for (int cc = 0; cc < kC; cc++)
                r = ffma2x(dup2(Psh[cc*kC + a]), tot2[cc], r);
            stcg64(g_R + ((size_t)b*kC + a)*kD + 2*t, r);
        }
        if (t == 0) g_cnt[b] = 0u;            // self-reset for graph replay
    }
}

// ===========================================================================
// K3: fused[i] = QB[c_i] + coef[c_i]*s_i + sum_{j<i} M[i][j]*s_j
//     QB[a] = R[a] + sum_c Q[a,c]*base[c]  (present classes only)
template<int CL>
static __device__ __forceinline__ void main_body(
    const float* __restrict__ src, float* __restrict__ outF,
    int t, int b, int chunk,
    ull* Q2, ull* coef2, ull* M2, ull* QBs, int* clsS, int* presentS)
{
    const int posBase = b*kL + chunkStart(chunk);
    if (t < CL) clsS[t] = g_cls[posBase + t];
    __syncthreads();

    // triangle coeffs M2[tri(i)+j] = Q[c_i, c_j], j<i  (<=45 entries)
    constexpr int TRI = CL*(CL-1)/2;
    if (t < TRI){
        int i = 1;
        while (i*(i+1)/2 <= t) i++;
        int j = t - i*(i-1)/2;
        M2[t] = Q2[clsS[i]*kQP + clsS[j]];
    }

    if (t == 0){
        unsigned mask = 0;
        #pragma unroll
        for (int i = 0; i < CL; i++) mask |= 1u << clsS[i];
        int n = 0;
        while (mask){ int a = __ffs(mask) - 1; mask &= mask - 1; presentS[1 + n++] = a; }
        presentS[0] = n;
    }

    // R preload (MLP over 21)
    const float* Rr = g_R + ((size_t)b*kC)*kD + 2*t;
    #pragma unroll
    for (int a = 0; a < kC; a++) QBs[a*kT + t] = ldcg64(Rr + (size_t)a*kD);

    // base = exclusive chunk-start class sums
    ull base[kC];
    {
        const float* cs = g_cs + ((size_t)(b*kChunks + chunk)*kC)*kD + 2*t;
        #pragma unroll
        for (int c = 0; c < kC; c++) base[c] = ldcg64(cs + (size_t)c*kD);
    }
    __syncthreads();

    // QB[a] for present classes only (warp-uniform count)
    const int nd = presentS[0];
    for (int k = 0; k < nd; k++){
        int a = presentS[1 + k];
        ull r = QBs[a*kT + t];
        #pragma unroll
        for (int c = 0; c < kC; c++)
            r = ffma2x(Q2[a*kQP + c], base[c], r);
        QBs[a*kT + t] = r;
    }

    const ull* sp = (const ull*)src + (size_t)posBase*kD2 + t;
    ull* fp = (ull*)outF + (size_t)posBase*kD2 + t;
    ull s[CL];
    #pragma unroll
    for (int i = 0; i < CL; i++) s[i] = sp[(size_t)i*kD2];

    #pragma unroll
    for (int i = 0; i < CL; i++){
        int c = clsS[i];                       // warp-uniform
        ull r = QBs[c*kT + t];
        r = ffma2x(coef2[c], s[i], r);
        const int tb = i*(i-1)/2;
        #pragma unroll
        for (int j = 0; j < i; j++)
            r = ffma2x(M2[tb + j], s[j], r);
        fp[(size_t)i*kD2] = r;
    }
}

__global__ void __launch_bounds__(kT) main_kernel(const float* __restrict__ P,
                                                  const float* __restrict__ src,
                                                  float* __restrict__ outF)
{
    __shared__ ull Q2[kC*kQP];
    __shared__ ull coef2[kC];
    __shared__ ull M2[45];
    __shared__ ull QBs[kC*kT];
    __shared__ int clsS[10];
    __shared__ int presentS[kC + 1];

    const int t = threadIdx.x, chunk = blockIdx.x, b = blockIdx.y;

    for (int idx = t; idx < kC*kC; idx += kT){
        int a = idx / kC, c = idx % kC;
        Q2[a*kQP + c] = dup2(P[a*kC + c] - P[c*kC + a]);
    }
    if (t < kC) coef2[t] = dup2((t != 0 ? 1.0f : 0.0f) - P[t*kC + t]);
    __syncthreads();

    if (chunk < 76) main_body<10>(src, outF, t, b, chunk, Q2, coef2, M2, QBs, clsS, presentS);
    else            main_body<9> (src, outF, t, b, chunk, Q2, coef2, M2, QBs, clsS, presentS);
}

// ===========================================================================
extern "C" void kernel_launch(void* const* d_in, const int* in_sizes, int n_in,
                              void* d_out, int out_size)
{
    const float* P   = (const float*)d_in[0];  // cls_r_prob [C,C]
    const float* src = (const float*)d_in[1];  // source [B,L,D]
    const void*  cls = d_in[2];                // class_idx [B,L]

    float* outF = (float*)d_out;
    const long long fusedElems = (long long)kB*kL*kD;
    float* outS = ((long long)out_size >= 2*fusedElems) ? (outF + fusedElems) : nullptr;

    convert_kernel<<<(kB*kL + 127)/128, 128>>>(cls);
    sum_kernel    <<<dim3(kChunks, kB), kT>>>(src, outS);
    scan_kernel   <<<kB*kC, kT>>>(P);
    main_kernel   <<<dim3(kChunks, kB), kT>>>(P, src, outF);
}

// round 10
// speedup vs baseline: 1.4068x; 1.2807x over previous
#include <cuda_runtime.h>

#define kB 16
#define kL 1444
#define kD 128
#define kD2 64          // float2 lanes per position
#define kC 21
#define kChunks 76
#define kCL 19          // 76*19 == 1444
#define kT 64
#define kQP 22          // padded Q row stride
#define kWaves 4        // 76 = 4*19 scan waves
#define kTRI 171        // 19*18/2

typedef unsigned long long ull;

// Device scratch (no allocations allowed)
__device__ float g_cs [kB*kChunks*kC*kD];  // chunk class sums -> exclusive prefix after scan
__device__ float g_tot[kB*kC*kD];          // per-batch class totals
__device__ float g_R  [kB*kC*kD];          // R[b][a][d] = sum_c P[c][a]*tot[b][c][d]
__device__ int   g_cls[kB*kL];
__device__ unsigned g_cnt[kB];             // per-batch arrival counters (self-resetting)

// ---- packed f32x2 helpers ---------------------------------------------------
static __device__ __forceinline__ ull fadd2(ull a, ull b){
    ull r; asm("add.rn.f32x2 %0,%1,%2;" : "=l"(r) : "l"(a), "l"(b)); return r;
}
static __device__ __forceinline__ ull ffma2x(ull a, ull b, ull c){
    ull r; asm("fma.rn.f32x2 %0,%1,%2,%3;" : "=l"(r) : "l"(a), "l"(b), "l"(c)); return r;
}
static __device__ __forceinline__ ull dup2(float x){
    ull r; asm("mov.b64 %0,{%1,%1};" : "=l"(r) : "f"(x)); return r;
}
static __device__ __forceinline__ ull ldcg64(const float* p){
    ull r; asm volatile("ld.global.cg.b64 %0,[%1];" : "=l"(r) : "l"(p)); return r;
}
static __device__ __forceinline__ void stcg64(float* p, ull v){
    asm volatile("st.global.cg.b64 [%0],%1;" :: "l"(p), "l"(v));
}

// ===========================================================================
// K1: per-chunk class sums + source passthrough + inline idx detect/convert.
__global__ void __launch_bounds__(kT) sum_kernel(const float* __restrict__ src,
                                                 const void*  __restrict__ cls,
                                                 float* __restrict__ outS)
{
    const int t = threadIdx.x;
    const int chunk = blockIdx.x, b = blockIdx.y;

    __shared__ int clsS[kCL];
    __shared__ ull acc[kC*kT];     // [class][thread] thread-private columns

    #pragma unroll
    for (int c = 0; c < kC; c++) acc[c*kT + t] = 0ULL;

    // dtype detection: 256 L2-resident words; any >20 impossible under int64
    int bad = 0;
    {
        const ull* p64 = (const ull*)cls;
        #pragma unroll
        for (int i = 0; i < 4; i++)
            if (p64[t + i*kT] > 20ULL) bad = 1;
    }
    int is32 = __syncthreads_or(bad);

    const int posBase = b*kL + chunk*kCL;
    if (t < kCL){
        int v = is32 ? ((const int*)cls)[posBase + t]
                     : (int)((const long long*)cls)[posBase + t];
        clsS[t] = v;
        g_cls[posBase + t] = v;
    }
    __syncthreads();

    const ull* sp = (const ull*)src + (size_t)posBase*kD2 + t;
    ull s[kCL];
    #pragma unroll
    for (int i = 0; i < kCL; i++) s[i] = sp[(size_t)i*kD2];

    if (outS){
        ull* osp = (ull*)outS + (size_t)posBase*kD2 + t;
        #pragma unroll
        for (int i = 0; i < kCL; i++) osp[(size_t)i*kD2] = s[i];
    }

    #pragma unroll
    for (int i = 0; i < kCL; i++){
        int c = clsS[i];                              // warp-uniform
        acc[c*kT + t] = fadd2(acc[c*kT + t], s[i]);   // private slot
    }

    float* cs = g_cs + ((size_t)(b*kChunks + chunk)*kC)*kD + 2*t;
    #pragma unroll
    for (int c = 0; c < kC; c++) stcg64(cs + (size_t)c*kD, acc[c*kT + t]);
}

// ===========================================================================
// K2: exclusive scan over 76 chunks per (b,c); last CTA per batch computes R.
__global__ void __launch_bounds__(kT) scan_kernel(const float* __restrict__ P)
{
    const int t = threadIdx.x;
    const int bc = blockIdx.x;                // 0..335
    const int b = bc / kC, c = bc % kC;

    float* base = g_cs + ((size_t)b*kChunks*kC + c)*kD + 2*t;
    const size_t stride = (size_t)kC*kD;

    ull run = 0ULL;
    #pragma unroll
    for (int w = 0; w < kWaves; w++){
        ull v[kCL];
        #pragma unroll
        for (int k = 0; k < kCL; k++) v[k] = ldcg64(base + (size_t)(w*kCL + k)*stride);
        #pragma unroll
        for (int k = 0; k < kCL; k++){
            stcg64(base + (size_t)(w*kCL + k)*stride, run);
            run = fadd2(run, v[k]);
        }
    }
    stcg64(g_tot + ((size_t)b*kC + c)*kD + 2*t, run);

    __threadfence();
    __shared__ int isLast;
    if (t == 0){
        unsigned old = atomicAdd(&g_cnt[b], 1u);
        isLast = (old == (unsigned)(kC - 1));
    }
    __syncthreads();

    if (isLast){
        __threadfence();
        __shared__ float Psh[kC*kC];
        for (int i = t; i < kC*kC; i += kT) Psh[i] = P[i];

        ull tot2[kC];
        #pragma unroll
        for (int cc = 0; cc < kC; cc++)
            tot2[cc] = ldcg64(g_tot + ((size_t)b*kC + cc)*kD + 2*t);
        __syncthreads();

        #pragma unroll
        for (int a = 0; a < kC; a++){
            ull r0 = 0ULL, r1 = 0ULL, r2 = 0ULL;
            #pragma unroll
            for (int cc = 0; cc < 21; cc += 3){
                r0 = ffma2x(dup2(Psh[(cc+0)*kC + a]), tot2[cc+0], r0);
                r1 = ffma2x(dup2(Psh[(cc+1)*kC + a]), tot2[cc+1], r1);
                r2 = ffma2x(dup2(Psh[(cc+2)*kC + a]), tot2[cc+2], r2);
            }
            stcg64(g_R + ((size_t)b*kC + a)*kD + 2*t, fadd2(fadd2(r0, r1), r2));
        }
        if (t == 0) g_cnt[b] = 0u;            // self-reset for graph replay
    }
}

// ===========================================================================
// K3: fused[i] = QB[c_i] + coef[c_i]*s_i + sum_{j<i} M[i][j]*s_j
//     QB[a] = R[a] + sum_c Q[a,c]*base[c]  (present classes only)
__global__ void __launch_bounds__(kT) main_kernel(const float* __restrict__ P,
                                                  const float* __restrict__ src,
                                                  float* __restrict__ outF)
{
    __shared__ ull Q2[kC*kQP];       // dup(P[a][c]-P[c][a])
    __shared__ ull coef2[kC];
    __shared__ ull M2[kTRI];
    __shared__ ull QBs[kC*kT];       // per-class combined vector (thread columns)
    __shared__ int clsS[kCL];
    __shared__ int presentS[kC + 1];

    const int t = threadIdx.x;
    const int chunk = blockIdx.x, b = blockIdx.y;

    for (int idx = t; idx < kC*kC; idx += kT){
        int a = idx / kC, c = idx % kC;
        Q2[a*kQP + c] = dup2(P[a*kC + c] - P[c*kC + a]);
    }
    if (t < kC) coef2[t] = dup2((t != 0 ? 1.0f : 0.0f) - P[t*kC + t]);

    const int posBase = b*kL + chunk*kCL;
    if (t < kCL) clsS[t] = g_cls[posBase + t];
    __syncthreads();

    // triangle coeffs M2[tri(i)+j] = Q[c_i, c_j], j<i
    for (int idx = t; idx < kTRI; idx += kT){
        int i = 1;
        while (i*(i+1)/2 <= idx) i++;
        int j = idx - i*(i-1)/2;
        M2[idx] = Q2[clsS[i]*kQP + clsS[j]];
    }

    if (t == 0){
        unsigned mask = 0;
        #pragma unroll
        for (int i = 0; i < kCL; i++) mask |= 1u << clsS[i];
        int n = 0;
        while (mask){ int a = __ffs(mask) - 1; mask &= mask - 1; presentS[1 + n++] = a; }
        presentS[0] = n;
    }

    // R preload (MLP over 21)
    const float* Rr = g_R + ((size_t)b*kC)*kD + 2*t;
    #pragma unroll
    for (int a = 0; a < kC; a++) QBs[a*kT + t] = ldcg64(Rr + (size_t)a*kD);

    // base = exclusive chunk-start class sums
    ull base[kC];
    {
        const float* cs = g_cs + ((size_t)(b*kChunks + chunk)*kC)*kD + 2*t;
        #pragma unroll
        for (int c = 0; c < kC; c++) base[c] = ldcg64(cs + (size_t)c*kD);
    }
    __syncthreads();

    // QB[a] for present classes only — 3-way split accumulators
    const int nd = presentS[0];
    for (int k = 0; k < nd; k++){
        int a = presentS[1 + k];             // warp-uniform
        const ull* qrow = Q2 + (size_t)a*kQP;
        ull r0 = QBs[a*kT + t], r1 = 0ULL, r2 = 0ULL;
        #pragma unroll
        for (int c = 0; c < 21; c += 3){
            r0 = ffma2x(qrow[c+0], base[c+0], r0);
            r1 = ffma2x(qrow[c+1], base[c+1], r1);
            r2 = ffma2x(qrow[c+2], base[c+2], r2);
        }
        QBs[a*kT + t] = fadd2(fadd2(r0, r1), r2);   // own column, no sync
    }

    const ull* sp = (const ull*)src + (size_t)posBase*kD2 + t;
    ull* fp = (ull*)outF + (size_t)posBase*kD2 + t;
    ull s[kCL];
    #pragma unroll
    for (int i = 0; i < kCL; i++) s[i] = sp[(size_t)i*kD2];

    #pragma unroll
    for (int i = 0; i < kCL; i++){
        int c = clsS[i];                     // warp-uniform
        const int tb = i*(i-1)/2;

        ull a0 = QBs[c*kT + t];
        ull a1 = ffma2x(coef2[c], s[i], 0ULL);
        ull a2 = 0ULL;

        // strict-lower triangle dot, 3 independent streams
        int j = 0;
        #pragma unroll
        for (; j + 2 < i; j += 3){
            a0 = ffma2x(M2[tb + j + 0], s[j + 0], a0);
            a1 = ffma2x(M2[tb + j + 1], s[j + 1], a1);
            a2 = ffma2x(M2[tb + j + 2], s[j + 2], a2);
        }
        #pragma unroll
        for (; j < i; j++)
            a0 = ffma2x(M2[tb + j], s[j], a0);

        fp[(size_t)i*kD2] = fadd2(fadd2(a0, a1), a2);
    }
}

// ===========================================================================
extern "C" void kernel_launch(void* const* d_in, const int* in_sizes, int n_in,
                              void* d_out, int out_size)
{
    const float* P   = (const float*)d_in[0];  // cls_r_prob [C,C]
    const float* src = (const float*)d_in[1];  // source [B,L,D]
    const void*  cls = d_in[2];                // class_idx [B,L]

    float* outF = (float*)d_out;
    const long long fusedElems = (long long)kB*kL*kD;
    float* outS = ((long long)out_size >= 2*fusedElems) ? (outF + fusedElems) : nullptr;

    sum_kernel <<<dim3(kChunks, kB), kT>>>(src, cls, outS);
    scan_kernel<<<kB*kC, kT>>>(P);
    main_kernel<<<dim3(kChunks, kB), kT>>>(P, src, outF);
}